// round 12
// baseline (speedup 1.0000x reference)
#include <cuda_runtime.h>
#include <cuda_bf16.h>

// DeepFilter: 5-tap complex FIR over first 256 freq bins + passthrough of the rest.
// spec:  [B=8][2][T=4096][F=481]  fp32
// coefs: [B=8][10][T=4096][256]   fp32   (10 = {real taps 0..4, imag taps 0..4})
// out:   [B=8][2][T=4096][F=481]  fp32
//
// Validated structure (R3 core + R10 hoisted tail loads): thread = freq bin,
// block = 2 time steps sharing a 6-row spec window in registers; tail-copy
// LOADS front-batched (16 independent LDGs/thread). This revision FORCES the
// 36-reg budget via __launch_bounds__(256, 7) to reach 7 blocks/SM (~85% occ)
// while keeping the deep front batch — the only untested (MLP, occ) cell.

#define NUM_FREQS 256
#define FRAME_SIZE 5
#define B_DIM 8
#define T_DIM 4096
#define F_TOTAL 481
#define F_TAIL (F_TOTAL - NUM_FREQS)   // 225

// Tail element idx (0..899) -> output offset for block (b, t0).
__device__ __forceinline__ int tail_offset(int b, int t0, int idx)
{
    const int r   = (idx >= 2 * F_TAIL) ? 1 : 0;
    const int rem = idx - r * (2 * F_TAIL);
    const int ch  = (rem >= F_TAIL) ? 1 : 0;
    const int j   = rem - ch * F_TAIL;
    return (b * 2 + ch) * T_DIM * F_TOTAL + (t0 + r) * F_TOTAL + NUM_FREQS + j;
}

__global__ __launch_bounds__(256, 7) void deepfilter_kernel(
    const float* __restrict__ spec,
    const float* __restrict__ coefs,
    float* __restrict__ out)
{
    const int b   = blockIdx.y;
    const int t0  = blockIdx.x << 1;         // 2 time steps per block
    const int f   = threadIdx.x;             // 0 .. 255

    const int spec_b0 = (b * 2) * T_DIM * F_TOTAL;     // real channel base
    const int spec_b1 = spec_b0 + T_DIM * F_TOTAL;     // imag channel base

    // ---- Front batch 1: tail-copy loads (independent of everything) ----
    // 2 rows * 2 ch * 225 = 900 elems over 256 threads -> up to 4 per thread.
    float tail_v[4];
#pragma unroll
    for (int u = 0; u < 4; ++u) {
        const int idx = threadIdx.x + u * 256;
        tail_v[u] = (idx < 2 * 2 * F_TAIL) ? spec[tail_offset(b, t0, idx)] : 0.0f;
    }

    // ---- Front batch 2: spec window, ts = t0-4 .. t0+1 (6 rows) ----
    float pr[6], pi[6];
#pragma unroll
    for (int k = 0; k < 6; ++k) {
        const int ts = t0 - 4 + k;
        if (ts >= 0) {
            const int so = ts * F_TOTAL + f;
            pr[k] = spec[spec_b0 + so];
            pi[k] = spec[spec_b1 + so];
        } else {
            pr[k] = 0.0f;
            pi[k] = 0.0f;
        }
    }

    const int c_row  = ((b * 10) * T_DIM + t0) * NUM_FREQS + f;
    const int c_kstr = T_DIM * NUM_FREQS;    // per-tap stride

    float re0 = 0.f, im0 = 0.f, re1 = 0.f, im1 = 0.f;
#pragma unroll
    for (int k = 0; k < FRAME_SIZE; ++k) {
        const float cr0 = __ldcs(&coefs[c_row + k * c_kstr]);
        const float ci0 = __ldcs(&coefs[c_row + (k + FRAME_SIZE) * c_kstr]);
        const float cr1 = __ldcs(&coefs[c_row + NUM_FREQS + k * c_kstr]);
        const float ci1 = __ldcs(&coefs[c_row + NUM_FREQS + (k + FRAME_SIZE) * c_kstr]);

        re0 = fmaf(pr[k],      cr0, re0);
        re0 = fmaf(-pi[k],     ci0, re0);
        im0 = fmaf(pi[k],      cr0, im0);
        im0 = fmaf(pr[k],      ci0, im0);

        re1 = fmaf(pr[k + 1],  cr1, re1);
        re1 = fmaf(-pi[k + 1], ci1, re1);
        im1 = fmaf(pi[k + 1],  cr1, im1);
        im1 = fmaf(pr[k + 1],  ci1, im1);
    }

    const int orow = t0 * F_TOTAL + f;
    out[spec_b0 + orow]           = re0;
    out[spec_b1 + orow]           = im0;
    out[spec_b0 + orow + F_TOTAL] = re1;
    out[spec_b1 + orow + F_TOTAL] = im1;

    // ---- Tail stores: recompute offsets (hidden behind store drain) ----
#pragma unroll
    for (int u = 0; u < 4; ++u) {
        const int idx = threadIdx.x + u * 256;
        if (idx < 2 * 2 * F_TAIL) {
            out[tail_offset(b, t0, idx)] = tail_v[u];
        }
    }
}

extern "C" void kernel_launch(void* const* d_in, const int* in_sizes, int n_in,
                              void* d_out, int out_size)
{
    const float* spec  = (const float*)d_in[0];
    const float* coefs = (const float*)d_in[1];
    float* out = (float*)d_out;

    dim3 grid(T_DIM / 2, B_DIM);
    dim3 block(256);
    deepfilter_kernel<<<grid, block>>>(spec, coefs, out);
}

// round 13
// speedup vs baseline: 1.2242x; 1.2242x over previous
#include <cuda_runtime.h>
#include <cuda_bf16.h>

// DeepFilter: 5-tap complex FIR over first 256 freq bins + passthrough of the rest.
// spec:  [B=8][2][T=4096][F=481]  fp32
// coefs: [B=8][10][T=4096][256]   fp32   (10 = {real taps 0..4, imag taps 0..4})
// out:   [B=8][2][T=4096][F=481]  fp32
//
// FINAL (validated R10, 93.6 us): DRAM-bound at ~6.2 TB/s = ~98% of the B300's
// measured ~6.3 TB/s LTS ceiling; traffic is compulsory (~545 MB).
// Structure: thread = freq bin (perfect lane coalescing), block = 2 consecutive
// time steps sharing the overlapping 6-row spec window in registers, and the
// tail-copy LOADS hoisted into the front batch (16 independent LDGs/thread).
// No launch-bounds floor: ptxas's natural 40-reg schedule preserves the front
// batch (forcing 32 regs serializes it: R4/R12 regressed to ~107 us kernel).

#define NUM_FREQS 256
#define FRAME_SIZE 5
#define B_DIM 8
#define T_DIM 4096
#define F_TOTAL 481
#define F_TAIL (F_TOTAL - NUM_FREQS)   // 225

__global__ __launch_bounds__(256) void deepfilter_kernel(
    const float* __restrict__ spec,
    const float* __restrict__ coefs,
    float* __restrict__ out)
{
    const int b   = blockIdx.y;
    const int t0  = blockIdx.x << 1;         // 2 time steps per block
    const int f   = threadIdx.x;             // 0 .. 255

    const int spec_b0 = (b * 2) * T_DIM * F_TOTAL;     // real channel base
    const int spec_b1 = spec_b0 + T_DIM * F_TOTAL;     // imag channel base

    // ---- Front batch 1: tail-copy loads (independent of everything) ----
    // 2 rows * 2 ch * 225 = 900 elems over 256 threads -> up to 4 per thread.
    float tail_v[4];
    int   tail_o[4];
#pragma unroll
    for (int u = 0; u < 4; ++u) {
        const int idx = threadIdx.x + u * 256;
        if (idx < 2 * 2 * F_TAIL) {
            const int r   = (idx >= 2 * F_TAIL) ? 1 : 0;
            const int rem = idx - r * (2 * F_TAIL);
            const int ch  = (rem >= F_TAIL) ? 1 : 0;
            const int j   = rem - ch * F_TAIL;
            const int o   = (b * 2 + ch) * T_DIM * F_TOTAL
                          + (t0 + r) * F_TOTAL + NUM_FREQS + j;
            tail_o[u] = o;
            tail_v[u] = spec[o];
        } else {
            tail_o[u] = -1;
            tail_v[u] = 0.0f;
        }
    }

    // ---- Front batch 2: spec window, ts = t0-4 .. t0+1 (6 rows) ----
    float pr[6], pi[6];
#pragma unroll
    for (int k = 0; k < 6; ++k) {
        const int ts = t0 - 4 + k;
        if (ts >= 0) {
            const int so = ts * F_TOTAL + f;
            pr[k] = spec[spec_b0 + so];
            pi[k] = spec[spec_b1 + so];
        } else {
            pr[k] = 0.0f;
            pi[k] = 0.0f;
        }
    }

    const int c_row  = ((b * 10) * T_DIM + t0) * NUM_FREQS + f;
    const int c_kstr = T_DIM * NUM_FREQS;    // per-tap stride

    float re0 = 0.f, im0 = 0.f, re1 = 0.f, im1 = 0.f;
#pragma unroll
    for (int k = 0; k < FRAME_SIZE; ++k) {
        const float cr0 = __ldcs(&coefs[c_row + k * c_kstr]);
        const float ci0 = __ldcs(&coefs[c_row + (k + FRAME_SIZE) * c_kstr]);
        const float cr1 = __ldcs(&coefs[c_row + NUM_FREQS + k * c_kstr]);
        const float ci1 = __ldcs(&coefs[c_row + NUM_FREQS + (k + FRAME_SIZE) * c_kstr]);

        re0 = fmaf(pr[k],      cr0, re0);
        re0 = fmaf(-pi[k],     ci0, re0);
        im0 = fmaf(pi[k],      cr0, im0);
        im0 = fmaf(pr[k],      ci0, im0);

        re1 = fmaf(pr[k + 1],  cr1, re1);
        re1 = fmaf(-pi[k + 1], ci1, re1);
        im1 = fmaf(pi[k + 1],  cr1, im1);
        im1 = fmaf(pr[k + 1],  ci1, im1);
    }

    const int orow = t0 * F_TOTAL + f;
    out[spec_b0 + orow]           = re0;
    out[spec_b1 + orow]           = im0;
    out[spec_b0 + orow + F_TOTAL] = re1;
    out[spec_b1 + orow + F_TOTAL] = im1;

    // ---- Tail stores (loads already done) ----
#pragma unroll
    for (int u = 0; u < 4; ++u) {
        if (tail_o[u] >= 0) {
            out[tail_o[u]] = tail_v[u];
        }
    }
}

extern "C" void kernel_launch(void* const* d_in, const int* in_sizes, int n_in,
                              void* d_out, int out_size)
{
    const float* spec  = (const float*)d_in[0];
    const float* coefs = (const float*)d_in[1];
    float* out = (float*)d_out;

    dim3 grid(T_DIM / 2, B_DIM);
    dim3 block(256);
    deepfilter_kernel<<<grid, block>>>(spec, coefs, out);
}